// round 1
// baseline (speedup 1.0000x reference)
#include <cuda_runtime.h>

#define Bn 4
#define Sn 4096
#define Hn 2048
#define Rn 64
#define HFn (7*Hn)      // 14336
#define HRn (Hn*Rn)     // 131072
#define FINF 3.402823466e+38f

// ---------------- scratch (device globals; no allocation allowed) ----------------
__device__ float g_s1[Bn*Hn], g_s2[Bn*Hn], g_s3[Bn*Hn], g_s4[Bn*Hn];
__device__ float g_mx[Bn*Hn], g_mn[Bn*Hn];
__device__ float g_rowsq[Bn*Sn];
__device__ float g_nrm[Bn];
__device__ float g_feats[Bn*HFn];
__device__ float g_h1pre[Bn*1024];
__device__ float g_h1[Bn*1024];
__device__ float g_h2[Bn*512];
__device__ float g_hf[Bn*256];
__device__ float g_U[Bn*HRn];   // U[b] as [H, R] row-major
__device__ float g_V[Bn*HRn];   // V[b] as [R, H] row-major
__device__ float g_T[Bn*Sn*Rn]; // T[b] as [S, R]
__device__ int   g_flag;        // 1 => base_transform is identity

// ---------------- helpers ----------------
__device__ __forceinline__ void atomicMaxF(float* a, float v){
    int* ai = (int*)a; int old = *ai;
    while (v > __int_as_float(old)) { old = atomicCAS(ai, old, __float_as_int(v)); }
}
__device__ __forceinline__ void atomicMinF(float* a, float v){
    int* ai = (int*)a; int old = *ai;
    while (v < __int_as_float(old)) { old = atomicCAS(ai, old, __float_as_int(v)); }
}
typedef unsigned long long u64;
__device__ __forceinline__ u64 pack_dup(float a){
    u64 r; asm("mov.b64 %0, {%1, %1};" : "=l"(r) : "f"(a)); return r;
}
__device__ __forceinline__ void fma2(u64& d, u64 a, u64 b){
    asm("fma.rn.f32x2 %0, %1, %2, %0;" : "+l"(d) : "l"(a), "l"(b));
}
__device__ __forceinline__ float2 unpack2(u64 v){
    float2 f; asm("mov.b64 {%0, %1}, %2;" : "=f"(f.x), "=f"(f.y) : "l"(v)); return f;
}

// ---------------- 1. reset ----------------
__global__ void k_reset(){
    int i = blockIdx.x*256 + threadIdx.x;
    if (i == 0) g_flag = 1;
    if (i < Bn*Hn){
        g_s1[i]=0.f; g_s2[i]=0.f; g_s3[i]=0.f; g_s4[i]=0.f;
        g_mx[i]=-FINF; g_mn[i]=FINF;
    }
    if (i < Bn*Sn) g_rowsq[i]=0.f;
    if (i < Bn*1024) g_h1pre[i]=0.f;
}

// ---------------- 2. identity check on base_transform ----------------
__global__ __launch_bounds__(1024) void k_check(const float* __restrict__ bt){
    int i = blockIdx.x*1024 + threadIdx.x;     // covers Hn*Hn exactly
    int r = i / Hn, c = i - r*Hn;
    float expect = (r == c) ? 1.f : 0.f;
    if (bt[i] != expect) g_flag = 0;
}

// ---------------- 3. fused single-pass stats ----------------
// grid = Bn * HT * SC = 4*8*16 = 512, block 256
__global__ __launch_bounds__(256) void k_stats(const float* __restrict__ x){
    const int HT = 8, SC = 16, SCH = Sn/SC;    // SCH = 256
    int blk = blockIdx.x;
    int b  = blk / (HT*SC);
    int ht = (blk / SC) % HT;
    int sc = blk % SC;
    int h  = ht*256 + threadIdx.x;
    int lane = threadIdx.x & 31;
    const float* xb = x + ((size_t)b*Sn)*Hn;
    float s1=0.f, s2=0.f, s3=0.f, s4=0.f, mx=-FINF, mn=FINF;
    int s0 = sc*SCH;
    #pragma unroll 4
    for (int s = s0; s < s0+SCH; s++){
        float v  = __ldg(xb + (size_t)s*Hn + h);
        float v2 = v*v;
        s1 += v; s2 += v2; s3 += v2*v; s4 += v2*v2;
        mx = fmaxf(mx, v); mn = fminf(mn, v);
        float r = v2;
        #pragma unroll
        for (int o = 16; o > 0; o >>= 1) r += __shfl_down_sync(0xffffffffu, r, o);
        if (lane == 0) atomicAdd(&g_rowsq[b*Sn + s], r);
    }
    int idx = b*Hn + h;
    atomicAdd(&g_s1[idx], s1); atomicAdd(&g_s2[idx], s2);
    atomicAdd(&g_s3[idx], s3); atomicAdd(&g_s4[idx], s4);
    atomicMaxF(&g_mx[idx], mx); atomicMinF(&g_mn[idx], mn);
}

// ---------------- 4. row-norm mean ----------------
__global__ void k_rownorm(){
    int b = blockIdx.x;
    float acc = 0.f;
    for (int s = threadIdx.x; s < Sn; s += 256) acc += sqrtf(g_rowsq[b*Sn + s]);
    __shared__ float sm[256];
    sm[threadIdx.x] = acc; __syncthreads();
    for (int st = 128; st > 0; st >>= 1){
        if (threadIdx.x < st) sm[threadIdx.x] += sm[threadIdx.x + st];
        __syncthreads();
    }
    if (threadIdx.x == 0) g_nrm[b] = sm[0] / (float)Sn;
}

// ---------------- 5. finalize features ----------------
__global__ void k_feats(){
    int i = blockIdx.x*256 + threadIdx.x;      // b*Hn + h
    int b = i / Hn, h = i - b*Hn;
    const float n = (float)Sn;
    float m1 = g_s1[i]/n, m2 = g_s2[i]/n, m3 = g_s3[i]/n, m4 = g_s4[i]/n;
    float mu2 = m2 - m1*m1; if (mu2 < 0.f) mu2 = 0.f;
    float sd  = sqrtf(mu2 * n/(n-1.f));        // ddof=1
    float mu3 = m3 - 3.f*m1*m2 + 2.f*m1*m1*m1;
    float mu4 = m4 - 4.f*m1*m3 + 6.f*m1*m1*m2 - 3.f*m1*m1*m1*m1;
    float skew = mu3 / (sd*sd*sd + 1e-8f);
    float kurt = mu4 / (sd*sd*sd*sd + 1e-8f) - 3.f;
    float* fb = g_feats + (size_t)b*HFn;
    fb[0*Hn+h]=m1; fb[1*Hn+h]=sd; fb[2*Hn+h]=g_nrm[b];
    fb[3*Hn+h]=g_mx[i]; fb[4*Hn+h]=g_mn[i]; fb[5*Hn+h]=skew; fb[6*Hn+h]=kurt;
}

// ---------------- 6. fc1: feats @ W1 + b1 (atomically accumulated) ----------------
// grid = 4 n-tiles * 64 k-chunks = 256, block 256, KC = 224
__global__ __launch_bounds__(256) void k_fc1(const float* __restrict__ W1, const float* __restrict__ b1){
    const int KC = 224;
    __shared__ float sf[Bn][KC];
    int nt = blockIdx.x >> 6, kc = blockIdx.x & 63;
    int n  = nt*256 + threadIdx.x;
    int k0 = kc*KC;
    for (int l = threadIdx.x; l < Bn*KC; l += 256){
        int bb = l / KC, kk = l - bb*KC;
        sf[bb][kk] = g_feats[(size_t)bb*HFn + k0 + kk];
    }
    __syncthreads();
    float init = (kc == 0) ? __ldg(b1 + n) : 0.f;
    float a0=init, a1=init, a2=init, a3=init;
    #pragma unroll 4
    for (int kk = 0; kk < KC; kk++){
        float w = __ldg(W1 + (size_t)(k0+kk)*1024 + n);
        a0 += sf[0][kk]*w; a1 += sf[1][kk]*w; a2 += sf[2][kk]*w; a3 += sf[3][kk]*w;
    }
    atomicAdd(&g_h1pre[0*1024+n], a0); atomicAdd(&g_h1pre[1*1024+n], a1);
    atomicAdd(&g_h1pre[2*1024+n], a2); atomicAdd(&g_h1pre[3*1024+n], a3);
}

// ---------------- 7. LN1 + ReLU ----------------
__global__ void k_ln1(const float* __restrict__ g1, const float* __restrict__ be1){
    int b = blockIdx.x;
    float v[4], s = 0.f, ss = 0.f;
    #pragma unroll
    for (int i = 0; i < 4; i++){
        v[i] = g_h1pre[b*1024 + i*256 + threadIdx.x];
        s += v[i]; ss += v[i]*v[i];
    }
    __shared__ float r1[256], r2[256];
    r1[threadIdx.x]=s; r2[threadIdx.x]=ss; __syncthreads();
    for (int st = 128; st > 0; st >>= 1){
        if (threadIdx.x < st){ r1[threadIdx.x]+=r1[threadIdx.x+st]; r2[threadIdx.x]+=r2[threadIdx.x+st]; }
        __syncthreads();
    }
    float mean = r1[0]/1024.f, var = r2[0]/1024.f - mean*mean;
    float inv = rsqrtf(var + 1e-5f);
    #pragma unroll
    for (int i = 0; i < 4; i++){
        int idx = i*256 + threadIdx.x;
        float y = (v[i]-mean)*inv*__ldg(g1+idx) + __ldg(be1+idx);
        g_h1[b*1024+idx] = fmaxf(y, 0.f);
    }
}

// ---------------- 8. fc2 + LN2 + ReLU (fused, one block per batch) ----------------
__global__ __launch_bounds__(512) void k_fc2(const float* __restrict__ W2, const float* __restrict__ b2,
                                             const float* __restrict__ g2, const float* __restrict__ be2){
    int b = blockIdx.x, n = threadIdx.x;
    __shared__ float sh[1024];
    for (int i = n; i < 1024; i += 512) sh[i] = g_h1[b*1024 + i];
    __syncthreads();
    float acc = __ldg(b2 + n);
    #pragma unroll 4
    for (int k = 0; k < 1024; k++) acc += sh[k]*__ldg(W2 + (size_t)k*512 + n);
    __shared__ float r1[512], r2[512];
    r1[n]=acc; r2[n]=acc*acc; __syncthreads();
    for (int st = 256; st > 0; st >>= 1){
        if (n < st){ r1[n]+=r1[n+st]; r2[n]+=r2[n+st]; }
        __syncthreads();
    }
    float mean = r1[0]/512.f, var = r2[0]/512.f - mean*mean;
    float y = (acc-mean)*rsqrtf(var+1e-5f)*__ldg(g2+n) + __ldg(be2+n);
    g_h2[b*512+n] = fmaxf(y, 0.f);
}

// ---------------- 9. fc3 + ReLU ----------------
__global__ void k_fc3(const float* __restrict__ W3, const float* __restrict__ b3){
    int b = blockIdx.x, n = threadIdx.x;
    __shared__ float sh[512];
    for (int i = n; i < 512; i += 256) sh[i] = g_h2[b*512 + i];
    __syncthreads();
    float acc = __ldg(b3 + n);
    #pragma unroll 4
    for (int k = 0; k < 512; k++) acc += sh[k]*__ldg(W3 + (size_t)k*256 + n);
    g_hf[b*256+n] = fmaxf(acc, 0.f);
}

// ---------------- 10. U,V generation (streams Wu,Wv once, 4 batches together) ----------------
__global__ __launch_bounds__(256) void k_uv(const float* __restrict__ Wu, const float* __restrict__ bu,
                                            const float* __restrict__ Wv, const float* __restrict__ bv,
                                            const float* __restrict__ su, const float* __restrict__ sv){
    __shared__ float sh[Bn*256];
    for (int i = threadIdx.x; i < Bn*256; i += 256) sh[i] = g_hf[i];
    __syncthreads();
    int half = blockIdx.x >> 9;                       // 0 -> U, 1 -> V
    int j = ((blockIdx.x & 511)*256) + threadIdx.x;   // [0, 131072)
    const float* W  = half ? Wv : Wu;
    const float* bb = half ? bv : bu;
    float sc = half ? __ldg(sv) : __ldg(su);
    float a0 = __ldg(bb + j); float a1=a0, a2=a0, a3=a0;
    #pragma unroll 4
    for (int k = 0; k < 256; k++){
        float w = __ldg(W + (size_t)k*HRn + j);
        a0 += sh[0*256+k]*w; a1 += sh[1*256+k]*w; a2 += sh[2*256+k]*w; a3 += sh[3*256+k]*w;
    }
    float* O = half ? g_V : g_U;
    O[0*(size_t)HRn+j]=a0*sc; O[1*(size_t)HRn+j]=a1*sc;
    O[2*(size_t)HRn+j]=a2*sc; O[3*(size_t)HRn+j]=a3*sc;
}

// ---------------- 11. general-base fallback: out = rw * (hidden @ base) ----------------
// No-ops (fast) when base is identity. grid = 4*64*32 = 8192
__global__ __launch_bounds__(256) void k_G(const float* __restrict__ x, const float* __restrict__ bt,
                                           const float* __restrict__ rw_p, float* __restrict__ out){
    if (g_flag) return;
    __shared__ float As[64][65];
    __shared__ float Bs[64][65];
    int blk = blockIdx.x;
    int b  = blk / 2048;
    int rem = blk - b*2048;
    int st = rem >> 5;       // 64 s-tiles
    int nt = rem & 31;       // 32 n-tiles
    int tid = threadIdx.x, tx = tid & 15, ty = tid >> 4;
    const float* xb = x + ((size_t)b*Sn + st*64)*Hn;
    float acc[4][4] = {};
    for (int kt = 0; kt < 32; kt++){
        #pragma unroll
        for (int r = 0; r < 16; r++){
            int l = r*256 + tid; int i = l >> 6, j = l & 63;
            As[i][j] = xb[(size_t)i*Hn + kt*64 + j];
            Bs[i][j] = bt[(size_t)(kt*64+i)*Hn + nt*64 + j];
        }
        __syncthreads();
        #pragma unroll
        for (int kk = 0; kk < 64; kk++){
            float a[4], bv[4];
            #pragma unroll
            for (int i = 0; i < 4; i++) a[i]  = As[ty*4+i][kk];
            #pragma unroll
            for (int j = 0; j < 4; j++) bv[j] = Bs[kk][tx*4+j];
            #pragma unroll
            for (int i = 0; i < 4; i++)
                #pragma unroll
                for (int j = 0; j < 4; j++) acc[i][j] += a[i]*bv[j];
        }
        __syncthreads();
    }
    float rwv = __ldg(rw_p);
    size_t base = ((size_t)b*Sn + st*64)*Hn + nt*64;
    #pragma unroll
    for (int i = 0; i < 4; i++)
        #pragma unroll
        for (int j = 0; j < 4; j++)
            out[base + (size_t)(ty*4+i)*Hn + tx*4+j] = rwv*acc[i][j];
}

// ---------------- 12. F1: T[b] = hidden[b] @ U[b]  (M=32 tiles, packed f32x2) ----------------
// grid = Bn * (Sn/32) = 512
__global__ __launch_bounds__(256) void k_F1(const float* __restrict__ x){
    __shared__ float As[32][65];
    __shared__ float Bs[64][64];
    int b  = blockIdx.x >> 7;
    int st = blockIdx.x & 127;
    int tid = threadIdx.x, tx = tid & 15, ty = tid >> 4;
    const float* xb = x + ((size_t)b*Sn + st*32)*Hn;
    const float* Ub = g_U + (size_t)b*HRn;
    u64 acc[2][2] = {{0ull,0ull},{0ull,0ull}};   // 0x0 bit pattern == (0.f, 0.f)
    for (int kt = 0; kt < 32; kt++){
        #pragma unroll
        for (int r = 0; r < 8; r++){
            int l = r*256 + tid; int i = l >> 6, j = l & 63;
            As[i][j] = __ldg(xb + (size_t)i*Hn + kt*64 + j);
        }
        #pragma unroll
        for (int r = 0; r < 16; r++){
            int l = r*256 + tid; int i = l >> 6, j = l & 63;
            Bs[i][j] = __ldg(Ub + (size_t)(kt*64+i)*Rn + j);
        }
        __syncthreads();
        #pragma unroll
        for (int kk = 0; kk < 64; kk++){
            u64 pb0 = *reinterpret_cast<const u64*>(&Bs[kk][tx*4]);
            u64 pb1 = *reinterpret_cast<const u64*>(&Bs[kk][tx*4+2]);
            u64 pa0 = pack_dup(As[ty*2+0][kk]);
            u64 pa1 = pack_dup(As[ty*2+1][kk]);
            fma2(acc[0][0], pa0, pb0); fma2(acc[0][1], pa0, pb1);
            fma2(acc[1][0], pa1, pb0); fma2(acc[1][1], pa1, pb1);
        }
        __syncthreads();
    }
    float* Tb = g_T + ((size_t)b*Sn + st*32)*Rn;
    #pragma unroll
    for (int i = 0; i < 2; i++){
        float2 v0 = unpack2(acc[i][0]), v1 = unpack2(acc[i][1]);
        float4 w = make_float4(v0.x, v0.y, v1.x, v1.y);
        *reinterpret_cast<float4*>(Tb + (size_t)(ty*2+i)*Rn + tx*4) = w;
    }
}

// ---------------- 13. F2: out = base_term + (1-rw) * T @ V  ----------------
// grid = Bn * 64 * 32 = 8192. base_term = rw*hidden (identity) else value k_G wrote.
__global__ __launch_bounds__(256) void k_F2(const float* __restrict__ x, const float* __restrict__ rw_p,
                                            float* __restrict__ out){
    __shared__ float Ts[64][65];
    __shared__ float Vs[64][64];
    int blk = blockIdx.x;
    int b  = blk / 2048;
    int rem = blk - b*2048;
    int st = rem >> 5;
    int kt = rem & 31;
    int tid = threadIdx.x, tx = tid & 15, ty = tid >> 4;
    const float* Tb = g_T + ((size_t)b*Sn + st*64)*Rn;
    const float* Vb = g_V + (size_t)b*HRn + kt*64;
    #pragma unroll
    for (int r = 0; r < 16; r++){
        int l = r*256 + tid; int i = l >> 6, j = l & 63;
        Ts[i][j] = __ldg(Tb + (size_t)i*Rn + j);
        Vs[i][j] = __ldg(Vb + (size_t)i*Hn + j);
    }
    __syncthreads();
    u64 acc[4][2] = {{0ull,0ull},{0ull,0ull},{0ull,0ull},{0ull,0ull}};
    #pragma unroll
    for (int kk = 0; kk < 64; kk++){
        u64 pb0 = *reinterpret_cast<const u64*>(&Vs[kk][tx*4]);
        u64 pb1 = *reinterpret_cast<const u64*>(&Vs[kk][tx*4+2]);
        #pragma unroll
        for (int i = 0; i < 4; i++){
            u64 pa = pack_dup(Ts[ty*4+i][kk]);
            fma2(acc[i][0], pa, pb0); fma2(acc[i][1], pa, pb1);
        }
    }
    float rwv = __ldg(rw_p);
    float cw  = 1.f - rwv;
    bool ident = (g_flag != 0);
    size_t base = ((size_t)b*Sn + st*64)*Hn + kt*64;
    #pragma unroll
    for (int i = 0; i < 4; i++){
        size_t off = base + (size_t)(ty*4+i)*Hn + tx*4;
        float2 v0 = unpack2(acc[i][0]), v1 = unpack2(acc[i][1]);
        float4 res;
        if (ident){
            float4 hv = *reinterpret_cast<const float4*>(x + off);
            res.x = rwv*hv.x + cw*v0.x; res.y = rwv*hv.y + cw*v0.y;
            res.z = rwv*hv.z + cw*v1.x; res.w = rwv*hv.w + cw*v1.y;
        } else {
            float4 pv = *reinterpret_cast<const float4*>(out + off);
            res.x = pv.x + cw*v0.x; res.y = pv.y + cw*v0.y;
            res.z = pv.z + cw*v1.x; res.w = pv.w + cw*v1.y;
        }
        *reinterpret_cast<float4*>(out + off) = res;
    }
}

// ---------------- launch ----------------
extern "C" void kernel_launch(void* const* d_in, const int* in_sizes, int n_in,
                              void* d_out, int out_size){
    const float* x   = (const float*)d_in[0];
    const float* W1  = (const float*)d_in[1];
    const float* b1  = (const float*)d_in[2];
    const float* g1  = (const float*)d_in[3];
    const float* be1 = (const float*)d_in[4];
    const float* W2  = (const float*)d_in[5];
    const float* b2  = (const float*)d_in[6];
    const float* g2  = (const float*)d_in[7];
    const float* be2 = (const float*)d_in[8];
    const float* W3  = (const float*)d_in[9];
    const float* b3  = (const float*)d_in[10];
    const float* Wu  = (const float*)d_in[11];
    const float* bu  = (const float*)d_in[12];
    const float* Wv  = (const float*)d_in[13];
    const float* bv  = (const float*)d_in[14];
    const float* su  = (const float*)d_in[15];
    const float* sv  = (const float*)d_in[16];
    const float* rw  = (const float*)d_in[17];
    const float* bt  = (const float*)d_in[18];
    float* out = (float*)d_out;

    k_reset  <<<64, 256>>>();
    k_check  <<<(Hn*Hn)/1024, 1024>>>(bt);
    k_stats  <<<512, 256>>>(x);
    k_rownorm<<<Bn, 256>>>();
    k_feats  <<<(Bn*Hn)/256, 256>>>();
    k_fc1    <<<256, 256>>>(W1, b1);
    k_ln1    <<<Bn, 256>>>(g1, be1);
    k_fc2    <<<Bn, 512>>>(W2, b2, g2, be2);
    k_fc3    <<<Bn, 256>>>(W3, b3);
    k_uv     <<<1024, 256>>>(Wu, bu, Wv, bv, su, sv);
    k_G      <<<8192, 256>>>(x, bt, rw, out);
    k_F1     <<<512, 256>>>(x);
    k_F2     <<<8192, 256>>>(x, rw, out);
}

// round 3
// speedup vs baseline: 1.1011x; 1.1011x over previous
#include <cuda_runtime.h>

#define Bn 4
#define Sn 4096
#define Hn 2048
#define Rn 64
#define HFn (7*Hn)      // 14336
#define HRn (Hn*Rn)     // 131072
#define FINF 3.402823466e+38f

// ---------------- scratch ----------------
__device__ float g_s1[Bn*Hn], g_s2[Bn*Hn], g_s3[Bn*Hn], g_s4[Bn*Hn];
__device__ float g_mx[Bn*Hn], g_mn[Bn*Hn];
__device__ float g_rowsq[Bn*Sn];
__device__ float g_nrm[Bn];
__device__ float g_feats[Bn*HFn];
__device__ float g_h1pre[Bn*1024], g_h1[Bn*1024];
__device__ float g_h2pre[Bn*512], g_h2[Bn*512];
__device__ float g_h3pre[Bn*256];
__device__ float g_U[Bn*HRn];   // U[b]: [H, R]
__device__ float g_V[Bn*HRn];   // V[b]: [R, H]
__device__ float g_T[Bn*Sn*Rn]; // T[b]: [S, R]  (1048576 floats = 262144 float4)
__device__ int   g_flag;

// ---------------- helpers ----------------
__device__ __forceinline__ void atomicMaxF(float* a, float v){
    int* ai = (int*)a; int old = *ai;
    while (v > __int_as_float(old)) { old = atomicCAS(ai, old, __float_as_int(v)); }
}
__device__ __forceinline__ void atomicMinF(float* a, float v){
    int* ai = (int*)a; int old = *ai;
    while (v < __int_as_float(old)) { old = atomicCAS(ai, old, __float_as_int(v)); }
}
typedef unsigned long long u64;
__device__ __forceinline__ u64 pack_dup(float a){
    u64 r; asm("mov.b64 %0, {%1, %1};" : "=l"(r) : "f"(a)); return r;
}
__device__ __forceinline__ void fma2(u64& d, u64 a, u64 b){
    asm("fma.rn.f32x2 %0, %1, %2, %0;" : "+l"(d) : "l"(a), "l"(b));
}
__device__ __forceinline__ float2 unpack2(u64 v){
    float2 f; asm("mov.b64 {%0, %1}, %2;" : "=f"(f.x), "=f"(f.y) : "l"(v)); return f;
}

// ---------------- 1. reset (also zeroes g_T for F1 atomics) ----------------
// grid 1024 x 256 = 262144 threads: one float4 of g_T each
__global__ void k_reset(){
    int i = blockIdx.x*256 + threadIdx.x;
    if (i == 0) g_flag = 1;
    if (i < Bn*Hn){
        g_s1[i]=0.f; g_s2[i]=0.f; g_s3[i]=0.f; g_s4[i]=0.f;
        g_mx[i]=-FINF; g_mn[i]=FINF;
    }
    if (i < Bn) g_nrm[i]=0.f;
    if (i < Bn*1024) g_h1pre[i]=0.f;
    if (i < Bn*512)  g_h2pre[i]=0.f;
    if (i < Bn*256)  g_h3pre[i]=0.f;
    float4* T4 = (float4*)g_T;           // 262144 float4 total
    T4[i] = make_float4(0.f,0.f,0.f,0.f);
}

// ---------------- 2. identity check ----------------
__global__ __launch_bounds__(1024) void k_check(const float* __restrict__ bt){
    int i = blockIdx.x*1024 + threadIdx.x;
    int r = i / Hn, c = i - r*Hn;
    float expect = (r == c) ? 1.f : 0.f;
    if (bt[i] != expect) g_flag = 0;
}

// ---------------- 3. row sum-of-squares: warp per row ----------------
// grid = Bn*Sn/8 = 2048, block 256 (8 warps = 8 rows)
__global__ __launch_bounds__(256) void k_rowsq(const float* __restrict__ x){
    int warp = threadIdx.x >> 5, lane = threadIdx.x & 31;
    int row = blockIdx.x*8 + warp;               // [0, Bn*Sn)
    const float4* xr = (const float4*)(x + (size_t)row*Hn);
    float acc = 0.f;
    #pragma unroll
    for (int i = 0; i < 16; i++){
        float4 v = __ldg(xr + lane + i*32);
        acc += v.x*v.x + v.y*v.y + v.z*v.z + v.w*v.w;
    }
    #pragma unroll
    for (int o = 16; o > 0; o >>= 1) acc += __shfl_down_sync(0xffffffffu, acc, o);
    if (lane == 0) g_rowsq[row] = acc;
}

// ---------------- 4. column stats (no shuffles) ----------------
// grid = Bn*8*16 = 512, block 256
__global__ __launch_bounds__(256) void k_stats(const float* __restrict__ x){
    const int SCH = 256;
    int blk = blockIdx.x;
    int b  = blk >> 7;
    int ht = (blk >> 4) & 7;
    int sc = blk & 15;
    int h  = ht*256 + threadIdx.x;
    const float* xb = x + ((size_t)b*Sn)*Hn + h;
    float s1=0.f, s2=0.f, s3=0.f, s4=0.f, mx=-FINF, mn=FINF;
    int s0 = sc*SCH;
    #pragma unroll 8
    for (int s = s0; s < s0+SCH; s++){
        float v  = __ldg(xb + (size_t)s*Hn);
        float v2 = v*v;
        s1 += v; s2 += v2; s3 += v2*v; s4 += v2*v2;
        mx = fmaxf(mx, v); mn = fminf(mn, v);
    }
    int idx = b*Hn + h;
    atomicAdd(&g_s1[idx], s1); atomicAdd(&g_s2[idx], s2);
    atomicAdd(&g_s3[idx], s3); atomicAdd(&g_s4[idx], s4);
    atomicMaxF(&g_mx[idx], mx); atomicMinF(&g_mn[idx], mn);
}

// ---------------- 5. norm mean: grid 64 ----------------
__global__ void k_nrm(){
    int b = blockIdx.x >> 4, c = blockIdx.x & 15;
    int s = c*256 + threadIdx.x;
    float v = sqrtf(g_rowsq[b*Sn + s]);
    __shared__ float sm[256];
    sm[threadIdx.x] = v; __syncthreads();
    for (int st = 128; st > 0; st >>= 1){
        if (threadIdx.x < st) sm[threadIdx.x] += sm[threadIdx.x + st];
        __syncthreads();
    }
    if (threadIdx.x == 0) atomicAdd(&g_nrm[b], sm[0]);
}

// ---------------- 6. finalize features ----------------
__global__ void k_feats(){
    int i = blockIdx.x*256 + threadIdx.x;      // b*Hn + h
    int b = i / Hn, h = i - b*Hn;
    const float n = (float)Sn;
    float m1 = g_s1[i]/n, m2 = g_s2[i]/n, m3 = g_s3[i]/n, m4 = g_s4[i]/n;
    float mu2 = m2 - m1*m1; if (mu2 < 0.f) mu2 = 0.f;
    float sd  = sqrtf(mu2 * n/(n-1.f));
    float mu3 = m3 - 3.f*m1*m2 + 2.f*m1*m1*m1;
    float mu4 = m4 - 4.f*m1*m3 + 6.f*m1*m1*m2 - 3.f*m1*m1*m1*m1;
    float skew = mu3 / (sd*sd*sd + 1e-8f);
    float kurt = mu4 / (sd*sd*sd*sd + 1e-8f) - 3.f;
    float* fb = g_feats + (size_t)b*HFn;
    fb[0*Hn+h]=m1; fb[1*Hn+h]=sd; fb[2*Hn+h]=g_nrm[b]*(1.f/n);
    fb[3*Hn+h]=g_mx[i]; fb[4*Hn+h]=g_mn[i]; fb[5*Hn+h]=skew; fb[6*Hn+h]=kurt;
}

// ---------------- 7. fc1: k-chunked with atomics ----------------
__global__ __launch_bounds__(256) void k_fc1(const float* __restrict__ W1, const float* __restrict__ b1){
    const int KC = 224;
    __shared__ float sf[Bn][KC];
    int nt = blockIdx.x >> 6, kc = blockIdx.x & 63;
    int n  = nt*256 + threadIdx.x;
    int k0 = kc*KC;
    for (int l = threadIdx.x; l < Bn*KC; l += 256){
        int bb = l / KC, kk = l - bb*KC;
        sf[bb][kk] = g_feats[(size_t)bb*HFn + k0 + kk];
    }
    __syncthreads();
    float init = (kc == 0) ? __ldg(b1 + n) : 0.f;
    float a0=init, a1=init, a2=init, a3=init;
    #pragma unroll 8
    for (int kk = 0; kk < KC; kk++){
        float w = __ldg(W1 + (size_t)(k0+kk)*1024 + n);
        a0 += sf[0][kk]*w; a1 += sf[1][kk]*w; a2 += sf[2][kk]*w; a3 += sf[3][kk]*w;
    }
    atomicAdd(&g_h1pre[0*1024+n], a0); atomicAdd(&g_h1pre[1*1024+n], a1);
    atomicAdd(&g_h1pre[2*1024+n], a2); atomicAdd(&g_h1pre[3*1024+n], a3);
}

// ---------------- 8. LN1 + ReLU ----------------
__global__ void k_ln1(const float* __restrict__ g1, const float* __restrict__ be1){
    int b = blockIdx.x;
    float v[4], s = 0.f, ss = 0.f;
    #pragma unroll
    for (int i = 0; i < 4; i++){
        v[i] = g_h1pre[b*1024 + i*256 + threadIdx.x];
        s += v[i]; ss += v[i]*v[i];
    }
    __shared__ float r1[256], r2[256];
    r1[threadIdx.x]=s; r2[threadIdx.x]=ss; __syncthreads();
    for (int st = 128; st > 0; st >>= 1){
        if (threadIdx.x < st){ r1[threadIdx.x]+=r1[threadIdx.x+st]; r2[threadIdx.x]+=r2[threadIdx.x+st]; }
        __syncthreads();
    }
    float mean = r1[0]/1024.f, var = r2[0]/1024.f - mean*mean;
    float inv = rsqrtf(var + 1e-5f);
    #pragma unroll
    for (int i = 0; i < 4; i++){
        int idx = i*256 + threadIdx.x;
        float y = (v[i]-mean)*inv*__ldg(g1+idx) + __ldg(be1+idx);
        g_h1[b*1024+idx] = fmaxf(y, 0.f);
    }
}

// ---------------- 9. fc2: k-split x8, atomics ----------------
// grid = 4b * 8kc = 32, block 512
__global__ __launch_bounds__(512) void k_fc2(const float* __restrict__ W2, const float* __restrict__ b2){
    int b = blockIdx.x >> 3, kc = blockIdx.x & 7;
    int n = threadIdx.x;
    __shared__ float sh[128];
    if (n < 128) sh[n] = g_h1[b*1024 + kc*128 + n];
    __syncthreads();
    float acc = (kc == 0) ? __ldg(b2 + n) : 0.f;
    #pragma unroll 8
    for (int k = 0; k < 128; k++)
        acc += sh[k]*__ldg(W2 + (size_t)(kc*128+k)*512 + n);
    atomicAdd(&g_h2pre[b*512+n], acc);
}

// ---------------- 10. LN2 + ReLU ----------------
__global__ __launch_bounds__(512) void k_ln2(const float* __restrict__ g2, const float* __restrict__ be2){
    int b = blockIdx.x, n = threadIdx.x;
    float acc = g_h2pre[b*512+n];
    __shared__ float r1[512], r2[512];
    r1[n]=acc; r2[n]=acc*acc; __syncthreads();
    for (int st = 256; st > 0; st >>= 1){
        if (n < st){ r1[n]+=r1[n+st]; r2[n]+=r2[n+st]; }
        __syncthreads();
    }
    float mean = r1[0]/512.f, var = r2[0]/512.f - mean*mean;
    float y = (acc-mean)*rsqrtf(var+1e-5f)*__ldg(g2+n) + __ldg(be2+n);
    g_h2[b*512+n] = fmaxf(y, 0.f);
}

// ---------------- 11. fc3: k-split x4, atomics (ReLU deferred to k_uv) ----------------
// grid = 4b * 4kc = 16, block 256
__global__ __launch_bounds__(256) void k_fc3(const float* __restrict__ W3, const float* __restrict__ b3){
    int b = blockIdx.x >> 2, kc = blockIdx.x & 3;
    int n = threadIdx.x;
    __shared__ float sh[128];
    if (n < 128) sh[n] = g_h2[b*512 + kc*128 + n];
    __syncthreads();
    float acc = (kc == 0) ? __ldg(b3 + n) : 0.f;
    #pragma unroll 8
    for (int k = 0; k < 128; k++)
        acc += sh[k]*__ldg(W3 + (size_t)(kc*128+k)*256 + n);
    atomicAdd(&g_h3pre[b*256+n], acc);
}

// ---------------- 12. U,V generation ----------------
__global__ __launch_bounds__(256) void k_uv(const float* __restrict__ Wu, const float* __restrict__ bu,
                                            const float* __restrict__ Wv, const float* __restrict__ bv,
                                            const float* __restrict__ su, const float* __restrict__ sv){
    __shared__ float sh[Bn*256];
    for (int i = threadIdx.x; i < Bn*256; i += 256) sh[i] = fmaxf(g_h3pre[i], 0.f);
    __syncthreads();
    int half = blockIdx.x >> 9;
    int j = ((blockIdx.x & 511)*256) + threadIdx.x;
    const float* W  = half ? Wv : Wu;
    const float* bb = half ? bv : bu;
    float sc = half ? __ldg(sv) : __ldg(su);
    float a0 = __ldg(bb + j); float a1=a0, a2=a0, a3=a0;
    #pragma unroll 8
    for (int k = 0; k < 256; k++){
        float w = __ldg(W + (size_t)k*HRn + j);
        a0 += sh[0*256+k]*w; a1 += sh[1*256+k]*w; a2 += sh[2*256+k]*w; a3 += sh[3*256+k]*w;
    }
    float* O = half ? g_V : g_U;
    O[0*(size_t)HRn+j]=a0*sc; O[1*(size_t)HRn+j]=a1*sc;
    O[2*(size_t)HRn+j]=a2*sc; O[3*(size_t)HRn+j]=a3*sc;
}

// ---------------- 13. general-base fallback (no-op when identity) ----------------
__global__ __launch_bounds__(256) void k_G(const float* __restrict__ x, const float* __restrict__ bt,
                                           const float* __restrict__ rw_p, float* __restrict__ out){
    if (g_flag) return;
    __shared__ float As[64][65];
    __shared__ float Bs[64][65];
    int blk = blockIdx.x;
    int b  = blk / 2048;
    int rem = blk - b*2048;
    int st = rem >> 5;
    int nt = rem & 31;
    int tid = threadIdx.x, tx = tid & 15, ty = tid >> 4;
    const float* xb = x + ((size_t)b*Sn + st*64)*Hn;
    float acc[4][4] = {};
    for (int kt = 0; kt < 32; kt++){
        #pragma unroll
        for (int r = 0; r < 16; r++){
            int l = r*256 + tid; int i = l >> 6, j = l & 63;
            As[i][j] = xb[(size_t)i*Hn + kt*64 + j];
            Bs[i][j] = bt[(size_t)(kt*64+i)*Hn + nt*64 + j];
        }
        __syncthreads();
        #pragma unroll
        for (int kk = 0; kk < 64; kk++){
            float a[4], bv[4];
            #pragma unroll
            for (int i = 0; i < 4; i++) a[i]  = As[ty*4+i][kk];
            #pragma unroll
            for (int j = 0; j < 4; j++) bv[j] = Bs[kk][tx*4+j];
            #pragma unroll
            for (int i = 0; i < 4; i++)
                #pragma unroll
                for (int j = 0; j < 4; j++) acc[i][j] += a[i]*bv[j];
        }
        __syncthreads();
    }
    float rwv = __ldg(rw_p);
    size_t base = ((size_t)b*Sn + st*64)*Hn + nt*64;
    #pragma unroll
    for (int i = 0; i < 4; i++)
        #pragma unroll
        for (int j = 0; j < 4; j++)
            out[base + (size_t)(ty*4+i)*Hn + tx*4+j] = rwv*acc[i][j];
}

// ---------------- 14. F1: T[b] += hidden[b] @ U[b], 64x64 tile, K-split x2 ----------------
// grid = Bn*64*2 = 512, block 256. acc: 2 rows x 8 cols (4 u64)
__global__ __launch_bounds__(256) void k_F1(const float* __restrict__ x){
    __shared__ float As[64][65];
    __shared__ float Bs[64][64];
    int blk = blockIdx.x;
    int b    = blk >> 7;
    int rem  = blk & 127;
    int st   = rem >> 1;
    int half = rem & 1;
    int tid = threadIdx.x, tx = tid & 7, ty = tid >> 3;   // tx: 8 col-groups, ty: 0..31 (2 rows each)
    const float* xb = x + ((size_t)b*Sn + st*64)*Hn;
    const float* Ub = g_U + (size_t)b*HRn;
    u64 acc[2][4] = {};
    int kt0 = half*16;
    for (int kt = kt0; kt < kt0+16; kt++){
        #pragma unroll
        for (int r = 0; r < 16; r++){
            int l = r*256 + tid; int i = l >> 6, j = l & 63;
            As[i][j] = __ldg(xb + (size_t)i*Hn + kt*64 + j);
            Bs[i][j] = __ldg(Ub + (size_t)(kt*64+i)*Rn + j);
        }
        __syncthreads();
        #pragma unroll
        for (int kk = 0; kk < 64; kk++){
            u64 pb[4];
            #pragma unroll
            for (int c = 0; c < 4; c++) pb[c] = *reinterpret_cast<const u64*>(&Bs[kk][tx*8 + c*2]);
            #pragma unroll
            for (int i = 0; i < 2; i++){
                u64 pa = pack_dup(As[ty*2+i][kk]);
                #pragma unroll
                for (int c = 0; c < 4; c++) fma2(acc[i][c], pa, pb[c]);
            }
        }
        __syncthreads();
    }
    float* Tb = g_T + ((size_t)b*Sn + st*64)*Rn;
    #pragma unroll
    for (int i = 0; i < 2; i++){
        float* dst = Tb + (size_t)(ty*2+i)*Rn + tx*8;
        #pragma unroll
        for (int c = 0; c < 4; c++){
            float2 v = unpack2(acc[i][c]);
            atomicAdd(dst + c*2,     v.x);
            atomicAdd(dst + c*2 + 1, v.y);
        }
    }
}

// ---------------- 15. F2: out = rw*x + (1-rw) * T @ V, 128x64 tile ----------------
// grid = Bn*32*32 = 4096, block 256. acc: 4 rows x 8 cols (4 u64)
__global__ __launch_bounds__(256) void k_F2(const float* __restrict__ x, const float* __restrict__ rw_p,
                                            float* __restrict__ out){
    __shared__ float Ts[128][65];
    __shared__ float Vs[64][64];
    int blk = blockIdx.x;
    int b  = blk >> 10;
    int rem = blk & 1023;
    int st = rem >> 5;        // 32 s-tiles of 128
    int nt = rem & 31;        // 32 n-tiles of 64
    int tid = threadIdx.x, tx = tid & 7, ty = tid >> 3;   // ty 0..31 (4 rows each)
    const float* Tb = g_T + ((size_t)b*Sn + st*128)*Rn;
    const float* Vb = g_V + (size_t)b*HRn + nt*64;
    #pragma unroll
    for (int r = 0; r < 32; r++){
        int l = r*256 + tid; int i = l >> 6, j = l & 63;
        Ts[i][j] = __ldg(Tb + (size_t)i*Rn + j);
    }
    #pragma unroll
    for (int r = 0; r < 16; r++){
        int l = r*256 + tid; int i = l >> 6, j = l & 63;
        Vs[i][j] = __ldg(Vb + (size_t)i*Hn + j);
    }
    __syncthreads();
    u64 acc[4][4] = {};
    #pragma unroll
    for (int kk = 0; kk < 64; kk++){
        u64 pb[4];
        #pragma unroll
        for (int c = 0; c < 4; c++) pb[c] = *reinterpret_cast<const u64*>(&Vs[kk][tx*8 + c*2]);
        #pragma unroll
        for (int i = 0; i < 4; i++){
            u64 pa = pack_dup(Ts[ty*4+i][kk]);
            #pragma unroll
            for (int c = 0; c < 4; c++) fma2(acc[i][c], pa, pb[c]);
        }
    }
    float rwv = __ldg(rw_p);
    float cw  = 1.f - rwv;
    bool ident = (g_flag != 0);
    size_t base = ((size_t)b*Sn + st*128)*Hn + nt*64 + tx*8;
    #pragma unroll
    for (int i = 0; i < 4; i++){
        size_t off = base + (size_t)(ty*4+i)*Hn;
        float2 v0 = unpack2(acc[i][0]), v1 = unpack2(acc[i][1]);
        float2 v2 = unpack2(acc[i][2]), v3 = unpack2(acc[i][3]);
        float4 r0, r1;
        if (ident){
            float4 h0 = *reinterpret_cast<const float4*>(x + off);
            float4 h1 = *reinterpret_cast<const float4*>(x + off + 4);
            r0.x = rwv*h0.x + cw*v0.x; r0.y = rwv*h0.y + cw*v0.y;
            r0.z = rwv*h0.z + cw*v1.x; r0.w = rwv*h0.w + cw*v1.y;
            r1.x = rwv*h1.x + cw*v2.x; r1.y = rwv*h1.y + cw*v2.y;
            r1.z = rwv*h1.z + cw*v3.x; r1.w = rwv*h1.w + cw*v3.y;
        } else {
            float4 p0 = *reinterpret_cast<const float4*>(out + off);
            float4 p1 = *reinterpret_cast<const float4*>(out + off + 4);
            r0.x = p0.x + cw*v0.x; r0.y = p0.y + cw*v0.y;
            r0.z = p0.z + cw*v1.x; r0.w = p0.w + cw*v1.y;
            r1.x = p1.x + cw*v2.x; r1.y = p1.y + cw*v2.y;
            r1.z = p1.z + cw*v3.x; r1.w = p1.w + cw*v3.y;
        }
        *reinterpret_cast<float4*>(out + off)     = r0;
        *reinterpret_cast<float4*>(out + off + 4) = r1;
    }
}

// ---------------- launch ----------------
extern "C" void kernel_launch(void* const* d_in, const int* in_sizes, int n_in,
                              void* d_out, int out_size){
    const float* x   = (const float*)d_in[0];
    const float* W1  = (const float*)d_in[1];
    const float* b1  = (const float*)d_in[2];
    const float* g1  = (const float*)d_in[3];
    const float* be1 = (const float*)d_in[4];
    const float* W2  = (const float*)d_in[5];
    const float* b2  = (const float*)d_in[6];
    const float* g2  = (const float*)d_in[7];
    const float* be2 = (const float*)d_in[8];
    const float* W3  = (const float*)d_in[9];
    const float* b3  = (const float*)d_in[10];
    const float* Wu  = (const float*)d_in[11];
    const float* bu  = (const float*)d_in[12];
    const float* Wv  = (const float*)d_in[13];
    const float* bv  = (const float*)d_in[14];
    const float* su  = (const float*)d_in[15];
    const float* sv  = (const float*)d_in[16];
    const float* rw  = (const float*)d_in[17];
    const float* bt  = (const float*)d_in[18];
    float* out = (float*)d_out;

    k_reset <<<1024, 256>>>();
    k_check <<<(Hn*Hn)/1024, 1024>>>(bt);
    k_rowsq <<<(Bn*Sn)/8, 256>>>(x);
    k_stats <<<512, 256>>>(x);
    k_nrm   <<<64, 256>>>();
    k_feats <<<(Bn*Hn)/256, 256>>>();
    k_fc1   <<<256, 256>>>(W1, b1);
    k_ln1   <<<Bn, 256>>>(g1, be1);
    k_fc2   <<<32, 512>>>(W2, b2);
    k_ln2   <<<Bn, 512>>>(g2, be2);
    k_fc3   <<<16, 256>>>(W3, b3);
    k_uv    <<<1024, 256>>>(Wu, bu, Wv, bv, su, sv);
    k_G     <<<8192, 256>>>(x, bt, rw, out);
    k_F1    <<<512, 256>>>(x);
    k_F2    <<<4096, 256>>>(x, rw, out);
}

// round 4
// speedup vs baseline: 1.1021x; 1.0010x over previous
#include <cuda_runtime.h>

#define Bn 4
#define Sn 4096
#define Hn 2048
#define Rn 64
#define HFn (7*Hn)      // 14336
#define HRn (Hn*Rn)     // 131072
#define FINF 3.402823466e+38f

// ---------------- scratch ----------------
__device__ float g_s1[Bn*Hn], g_s2[Bn*Hn], g_s3[Bn*Hn], g_s4[Bn*Hn];
__device__ float g_mx[Bn*Hn], g_mn[Bn*Hn];
__device__ float g_rowsq[Bn*Sn];
__device__ float g_nrm[Bn];
__device__ float g_feats[Bn*HFn];
__device__ float g_h1pre[Bn*1024], g_h1[Bn*1024];
__device__ float g_h2pre[Bn*512], g_h2[Bn*512];
__device__ float g_h3pre[Bn*256];
__device__ float g_U[Bn*HRn];   // U[b]: [H, R]
__device__ float g_V[Bn*HRn];   // V[b]: [R, H]
__device__ float g_T[Bn*Sn*Rn]; // T[b]: [S, R]  (1048576 floats = 262144 float4)
__device__ int   g_flag;

// ---------------- helpers ----------------
__device__ __forceinline__ void atomicMaxF(float* a, float v){
    int* ai = (int*)a; int old = *ai;
    while (v > __int_as_float(old)) { old = atomicCAS(ai, old, __float_as_int(v)); }
}
__device__ __forceinline__ void atomicMinF(float* a, float v){
    int* ai = (int*)a; int old = *ai;
    while (v < __int_as_float(old)) { old = atomicCAS(ai, old, __float_as_int(v)); }
}
typedef unsigned long long u64;
__device__ __forceinline__ u64 pack_dup(float a){
    u64 r; asm("mov.b64 %0, {%1, %1};" : "=l"(r) : "f"(a)); return r;
}
__device__ __forceinline__ void fma2(u64& d, u64 a, u64 b){
    asm("fma.rn.f32x2 %0, %1, %2, %0;" : "+l"(d) : "l"(a), "l"(b));
}
__device__ __forceinline__ float2 unpack2(u64 v){
    float2 f; asm("mov.b64 {%0, %1}, %2;" : "=f"(f.x), "=f"(f.y) : "l"(v)); return f;
}

// ---------------- 1. reset (also zeroes g_T for F1 atomics) ----------------
// grid 1024 x 256 = 262144 threads: one float4 of g_T each
__global__ void k_reset(){
    int i = blockIdx.x*256 + threadIdx.x;
    if (i == 0) g_flag = 1;
    if (i < Bn*Hn){
        g_s1[i]=0.f; g_s2[i]=0.f; g_s3[i]=0.f; g_s4[i]=0.f;
        g_mx[i]=-FINF; g_mn[i]=FINF;
    }
    if (i < Bn) g_nrm[i]=0.f;
    if (i < Bn*1024) g_h1pre[i]=0.f;
    if (i < Bn*512)  g_h2pre[i]=0.f;
    if (i < Bn*256)  g_h3pre[i]=0.f;
    float4* T4 = (float4*)g_T;           // 262144 float4 total
    T4[i] = make_float4(0.f,0.f,0.f,0.f);
}

// ---------------- 2. identity check ----------------
__global__ __launch_bounds__(1024) void k_check(const float* __restrict__ bt){
    int i = blockIdx.x*1024 + threadIdx.x;
    int r = i / Hn, c = i - r*Hn;
    float expect = (r == c) ? 1.f : 0.f;
    if (bt[i] != expect) g_flag = 0;
}

// ---------------- 3. row sum-of-squares: warp per row ----------------
// grid = Bn*Sn/8 = 2048, block 256 (8 warps = 8 rows)
__global__ __launch_bounds__(256) void k_rowsq(const float* __restrict__ x){
    int warp = threadIdx.x >> 5, lane = threadIdx.x & 31;
    int row = blockIdx.x*8 + warp;               // [0, Bn*Sn)
    const float4* xr = (const float4*)(x + (size_t)row*Hn);
    float acc = 0.f;
    #pragma unroll
    for (int i = 0; i < 16; i++){
        float4 v = __ldg(xr + lane + i*32);
        acc += v.x*v.x + v.y*v.y + v.z*v.z + v.w*v.w;
    }
    #pragma unroll
    for (int o = 16; o > 0; o >>= 1) acc += __shfl_down_sync(0xffffffffu, acc, o);
    if (lane == 0) g_rowsq[row] = acc;
}

// ---------------- 4. column stats (no shuffles) ----------------
// grid = Bn*8*16 = 512, block 256
__global__ __launch_bounds__(256) void k_stats(const float* __restrict__ x){
    const int SCH = 256;
    int blk = blockIdx.x;
    int b  = blk >> 7;
    int ht = (blk >> 4) & 7;
    int sc = blk & 15;
    int h  = ht*256 + threadIdx.x;
    const float* xb = x + ((size_t)b*Sn)*Hn + h;
    float s1=0.f, s2=0.f, s3=0.f, s4=0.f, mx=-FINF, mn=FINF;
    int s0 = sc*SCH;
    #pragma unroll 8
    for (int s = s0; s < s0+SCH; s++){
        float v  = __ldg(xb + (size_t)s*Hn);
        float v2 = v*v;
        s1 += v; s2 += v2; s3 += v2*v; s4 += v2*v2;
        mx = fmaxf(mx, v); mn = fminf(mn, v);
    }
    int idx = b*Hn + h;
    atomicAdd(&g_s1[idx], s1); atomicAdd(&g_s2[idx], s2);
    atomicAdd(&g_s3[idx], s3); atomicAdd(&g_s4[idx], s4);
    atomicMaxF(&g_mx[idx], mx); atomicMinF(&g_mn[idx], mn);
}

// ---------------- 5. norm mean: grid 64 ----------------
__global__ void k_nrm(){
    int b = blockIdx.x >> 4, c = blockIdx.x & 15;
    int s = c*256 + threadIdx.x;
    float v = sqrtf(g_rowsq[b*Sn + s]);
    __shared__ float sm[256];
    sm[threadIdx.x] = v; __syncthreads();
    for (int st = 128; st > 0; st >>= 1){
        if (threadIdx.x < st) sm[threadIdx.x] += sm[threadIdx.x + st];
        __syncthreads();
    }
    if (threadIdx.x == 0) atomicAdd(&g_nrm[b], sm[0]);
}

// ---------------- 6. finalize features ----------------
__global__ void k_feats(){
    int i = blockIdx.x*256 + threadIdx.x;      // b*Hn + h
    int b = i / Hn, h = i - b*Hn;
    const float n = (float)Sn;
    float m1 = g_s1[i]/n, m2 = g_s2[i]/n, m3 = g_s3[i]/n, m4 = g_s4[i]/n;
    float mu2 = m2 - m1*m1; if (mu2 < 0.f) mu2 = 0.f;
    float sd  = sqrtf(mu2 * n/(n-1.f));
    float mu3 = m3 - 3.f*m1*m2 + 2.f*m1*m1*m1;
    float mu4 = m4 - 4.f*m1*m3 + 6.f*m1*m1*m2 - 3.f*m1*m1*m1*m1;
    float skew = mu3 / (sd*sd*sd + 1e-8f);
    float kurt = mu4 / (sd*sd*sd*sd + 1e-8f) - 3.f;
    float* fb = g_feats + (size_t)b*HFn;
    fb[0*Hn+h]=m1; fb[1*Hn+h]=sd; fb[2*Hn+h]=g_nrm[b]*(1.f/n);
    fb[3*Hn+h]=g_mx[i]; fb[4*Hn+h]=g_mn[i]; fb[5*Hn+h]=skew; fb[6*Hn+h]=kurt;
}

// ---------------- 7. fc1: k-chunked with atomics ----------------
__global__ __launch_bounds__(256) void k_fc1(const float* __restrict__ W1, const float* __restrict__ b1){
    const int KC = 224;
    __shared__ float sf[Bn][KC];
    int nt = blockIdx.x >> 6, kc = blockIdx.x & 63;
    int n  = nt*256 + threadIdx.x;
    int k0 = kc*KC;
    for (int l = threadIdx.x; l < Bn*KC; l += 256){
        int bb = l / KC, kk = l - bb*KC;
        sf[bb][kk] = g_feats[(size_t)bb*HFn + k0 + kk];
    }
    __syncthreads();
    float init = (kc == 0) ? __ldg(b1 + n) : 0.f;
    float a0=init, a1=init, a2=init, a3=init;
    #pragma unroll 8
    for (int kk = 0; kk < KC; kk++){
        float w = __ldg(W1 + (size_t)(k0+kk)*1024 + n);
        a0 += sf[0][kk]*w; a1 += sf[1][kk]*w; a2 += sf[2][kk]*w; a3 += sf[3][kk]*w;
    }
    atomicAdd(&g_h1pre[0*1024+n], a0); atomicAdd(&g_h1pre[1*1024+n], a1);
    atomicAdd(&g_h1pre[2*1024+n], a2); atomicAdd(&g_h1pre[3*1024+n], a3);
}

// ---------------- 8. LN1 + ReLU ----------------
__global__ void k_ln1(const float* __restrict__ g1, const float* __restrict__ be1){
    int b = blockIdx.x;
    float v[4], s = 0.f, ss = 0.f;
    #pragma unroll
    for (int i = 0; i < 4; i++){
        v[i] = g_h1pre[b*1024 + i*256 + threadIdx.x];
        s += v[i]; ss += v[i]*v[i];
    }
    __shared__ float r1[256], r2[256];
    r1[threadIdx.x]=s; r2[threadIdx.x]=ss; __syncthreads();
    for (int st = 128; st > 0; st >>= 1){
        if (threadIdx.x < st){ r1[threadIdx.x]+=r1[threadIdx.x+st]; r2[threadIdx.x]+=r2[threadIdx.x+st]; }
        __syncthreads();
    }
    float mean = r1[0]/1024.f, var = r2[0]/1024.f - mean*mean;
    float inv = rsqrtf(var + 1e-5f);
    #pragma unroll
    for (int i = 0; i < 4; i++){
        int idx = i*256 + threadIdx.x;
        float y = (v[i]-mean)*inv*__ldg(g1+idx) + __ldg(be1+idx);
        g_h1[b*1024+idx] = fmaxf(y, 0.f);
    }
}

// ---------------- 9. fc2: k-split x8, atomics ----------------
// grid = 4b * 8kc = 32, block 512
__global__ __launch_bounds__(512) void k_fc2(const float* __restrict__ W2, const float* __restrict__ b2){
    int b = blockIdx.x >> 3, kc = blockIdx.x & 7;
    int n = threadIdx.x;
    __shared__ float sh[128];
    if (n < 128) sh[n] = g_h1[b*1024 + kc*128 + n];
    __syncthreads();
    float acc = (kc == 0) ? __ldg(b2 + n) : 0.f;
    #pragma unroll 8
    for (int k = 0; k < 128; k++)
        acc += sh[k]*__ldg(W2 + (size_t)(kc*128+k)*512 + n);
    atomicAdd(&g_h2pre[b*512+n], acc);
}

// ---------------- 10. LN2 + ReLU ----------------
__global__ __launch_bounds__(512) void k_ln2(const float* __restrict__ g2, const float* __restrict__ be2){
    int b = blockIdx.x, n = threadIdx.x;
    float acc = g_h2pre[b*512+n];
    __shared__ float r1[512], r2[512];
    r1[n]=acc; r2[n]=acc*acc; __syncthreads();
    for (int st = 256; st > 0; st >>= 1){
        if (n < st){ r1[n]+=r1[n+st]; r2[n]+=r2[n+st]; }
        __syncthreads();
    }
    float mean = r1[0]/512.f, var = r2[0]/512.f - mean*mean;
    float y = (acc-mean)*rsqrtf(var+1e-5f)*__ldg(g2+n) + __ldg(be2+n);
    g_h2[b*512+n] = fmaxf(y, 0.f);
}

// ---------------- 11. fc3: k-split x4, atomics (ReLU deferred to k_uv) ----------------
// grid = 4b * 4kc = 16, block 256
__global__ __launch_bounds__(256) void k_fc3(const float* __restrict__ W3, const float* __restrict__ b3){
    int b = blockIdx.x >> 2, kc = blockIdx.x & 3;
    int n = threadIdx.x;
    __shared__ float sh[128];
    if (n < 128) sh[n] = g_h2[b*512 + kc*128 + n];
    __syncthreads();
    float acc = (kc == 0) ? __ldg(b3 + n) : 0.f;
    #pragma unroll 8
    for (int k = 0; k < 128; k++)
        acc += sh[k]*__ldg(W3 + (size_t)(kc*128+k)*256 + n);
    atomicAdd(&g_h3pre[b*256+n], acc);
}

// ---------------- 12. U,V generation ----------------
__global__ __launch_bounds__(256) void k_uv(const float* __restrict__ Wu, const float* __restrict__ bu,
                                            const float* __restrict__ Wv, const float* __restrict__ bv,
                                            const float* __restrict__ su, const float* __restrict__ sv){
    __shared__ float sh[Bn*256];
    for (int i = threadIdx.x; i < Bn*256; i += 256) sh[i] = fmaxf(g_h3pre[i], 0.f);
    __syncthreads();
    int half = blockIdx.x >> 9;
    int j = ((blockIdx.x & 511)*256) + threadIdx.x;
    const float* W  = half ? Wv : Wu;
    const float* bb = half ? bv : bu;
    float sc = half ? __ldg(sv) : __ldg(su);
    float a0 = __ldg(bb + j); float a1=a0, a2=a0, a3=a0;
    #pragma unroll 8
    for (int k = 0; k < 256; k++){
        float w = __ldg(W + (size_t)k*HRn + j);
        a0 += sh[0*256+k]*w; a1 += sh[1*256+k]*w; a2 += sh[2*256+k]*w; a3 += sh[3*256+k]*w;
    }
    float* O = half ? g_V : g_U;
    O[0*(size_t)HRn+j]=a0*sc; O[1*(size_t)HRn+j]=a1*sc;
    O[2*(size_t)HRn+j]=a2*sc; O[3*(size_t)HRn+j]=a3*sc;
}

// ---------------- 13. general-base fallback (no-op when identity) ----------------
__global__ __launch_bounds__(256) void k_G(const float* __restrict__ x, const float* __restrict__ bt,
                                           const float* __restrict__ rw_p, float* __restrict__ out){
    if (g_flag) return;
    __shared__ float As[64][65];
    __shared__ float Bs[64][65];
    int blk = blockIdx.x;
    int b  = blk / 2048;
    int rem = blk - b*2048;
    int st = rem >> 5;
    int nt = rem & 31;
    int tid = threadIdx.x, tx = tid & 15, ty = tid >> 4;
    const float* xb = x + ((size_t)b*Sn + st*64)*Hn;
    float acc[4][4] = {};
    for (int kt = 0; kt < 32; kt++){
        #pragma unroll
        for (int r = 0; r < 16; r++){
            int l = r*256 + tid; int i = l >> 6, j = l & 63;
            As[i][j] = xb[(size_t)i*Hn + kt*64 + j];
            Bs[i][j] = bt[(size_t)(kt*64+i)*Hn + nt*64 + j];
        }
        __syncthreads();
        #pragma unroll
        for (int kk = 0; kk < 64; kk++){
            float a[4], bv[4];
            #pragma unroll
            for (int i = 0; i < 4; i++) a[i]  = As[ty*4+i][kk];
            #pragma unroll
            for (int j = 0; j < 4; j++) bv[j] = Bs[kk][tx*4+j];
            #pragma unroll
            for (int i = 0; i < 4; i++)
                #pragma unroll
                for (int j = 0; j < 4; j++) acc[i][j] += a[i]*bv[j];
        }
        __syncthreads();
    }
    float rwv = __ldg(rw_p);
    size_t base = ((size_t)b*Sn + st*64)*Hn + nt*64;
    #pragma unroll
    for (int i = 0; i < 4; i++)
        #pragma unroll
        for (int j = 0; j < 4; j++)
            out[base + (size_t)(ty*4+i)*Hn + tx*4+j] = rwv*acc[i][j];
}

// ---------------- 14. F1: T[b] += hidden[b] @ U[b], 64x64 tile, K-split x2 ----------------
// grid = Bn*64*2 = 512, block 256. acc: 2 rows x 8 cols (4 u64)
__global__ __launch_bounds__(256) void k_F1(const float* __restrict__ x){
    __shared__ float As[64][65];
    __shared__ float Bs[64][64];
    int blk = blockIdx.x;
    int b    = blk >> 7;
    int rem  = blk & 127;
    int st   = rem >> 1;
    int half = rem & 1;
    int tid = threadIdx.x, tx = tid & 7, ty = tid >> 3;   // tx: 8 col-groups, ty: 0..31 (2 rows each)
    const float* xb = x + ((size_t)b*Sn + st*64)*Hn;
    const float* Ub = g_U + (size_t)b*HRn;
    u64 acc[2][4] = {};
    int kt0 = half*16;
    for (int kt = kt0; kt < kt0+16; kt++){
        #pragma unroll
        for (int r = 0; r < 16; r++){
            int l = r*256 + tid; int i = l >> 6, j = l & 63;
            As[i][j] = __ldg(xb + (size_t)i*Hn + kt*64 + j);
            Bs[i][j] = __ldg(Ub + (size_t)(kt*64+i)*Rn + j);
        }
        __syncthreads();
        #pragma unroll
        for (int kk = 0; kk < 64; kk++){
            u64 pb[4];
            #pragma unroll
            for (int c = 0; c < 4; c++) pb[c] = *reinterpret_cast<const u64*>(&Bs[kk][tx*8 + c*2]);
            #pragma unroll
            for (int i = 0; i < 2; i++){
                u64 pa = pack_dup(As[ty*2+i][kk]);
                #pragma unroll
                for (int c = 0; c < 4; c++) fma2(acc[i][c], pa, pb[c]);
            }
        }
        __syncthreads();
    }
    float* Tb = g_T + ((size_t)b*Sn + st*64)*Rn;
    #pragma unroll
    for (int i = 0; i < 2; i++){
        float* dst = Tb + (size_t)(ty*2+i)*Rn + tx*8;
        #pragma unroll
        for (int c = 0; c < 4; c++){
            float2 v = unpack2(acc[i][c]);
            atomicAdd(dst + c*2,     v.x);
            atomicAdd(dst + c*2 + 1, v.y);
        }
    }
}

// ---------------- 15. F2: out = rw*x + (1-rw) * T @ V, 128x64 tile ----------------
// grid = Bn*32*32 = 4096, block 256. acc: 4 rows x 8 cols (4 u64)
__global__ __launch_bounds__(256) void k_F2(const float* __restrict__ x, const float* __restrict__ rw_p,
                                            float* __restrict__ out){
    __shared__ float Ts[128][65];
    __shared__ float Vs[64][64];
    int blk = blockIdx.x;
    int b  = blk >> 10;
    int rem = blk & 1023;
    int st = rem >> 5;        // 32 s-tiles of 128
    int nt = rem & 31;        // 32 n-tiles of 64
    int tid = threadIdx.x, tx = tid & 7, ty = tid >> 3;   // ty 0..31 (4 rows each)
    const float* Tb = g_T + ((size_t)b*Sn + st*128)*Rn;
    const float* Vb = g_V + (size_t)b*HRn + nt*64;
    #pragma unroll
    for (int r = 0; r < 32; r++){
        int l = r*256 + tid; int i = l >> 6, j = l & 63;
        Ts[i][j] = __ldg(Tb + (size_t)i*Rn + j);
    }
    #pragma unroll
    for (int r = 0; r < 16; r++){
        int l = r*256 + tid; int i = l >> 6, j = l & 63;
        Vs[i][j] = __ldg(Vb + (size_t)i*Hn + j);
    }
    __syncthreads();
    u64 acc[4][4] = {};
    #pragma unroll
    for (int kk = 0; kk < 64; kk++){
        u64 pb[4];
        #pragma unroll
        for (int c = 0; c < 4; c++) pb[c] = *reinterpret_cast<const u64*>(&Vs[kk][tx*8 + c*2]);
        #pragma unroll
        for (int i = 0; i < 4; i++){
            u64 pa = pack_dup(Ts[ty*4+i][kk]);
            #pragma unroll
            for (int c = 0; c < 4; c++) fma2(acc[i][c], pa, pb[c]);
        }
    }
    float rwv = __ldg(rw_p);
    float cw  = 1.f - rwv;
    bool ident = (g_flag != 0);
    size_t base = ((size_t)b*Sn + st*128)*Hn + nt*64 + tx*8;
    #pragma unroll
    for (int i = 0; i < 4; i++){
        size_t off = base + (size_t)(ty*4+i)*Hn;
        float2 v0 = unpack2(acc[i][0]), v1 = unpack2(acc[i][1]);
        float2 v2 = unpack2(acc[i][2]), v3 = unpack2(acc[i][3]);
        float4 r0, r1;
        if (ident){
            float4 h0 = *reinterpret_cast<const float4*>(x + off);
            float4 h1 = *reinterpret_cast<const float4*>(x + off + 4);
            r0.x = rwv*h0.x + cw*v0.x; r0.y = rwv*h0.y + cw*v0.y;
            r0.z = rwv*h0.z + cw*v1.x; r0.w = rwv*h0.w + cw*v1.y;
            r1.x = rwv*h1.x + cw*v2.x; r1.y = rwv*h1.y + cw*v2.y;
            r1.z = rwv*h1.z + cw*v3.x; r1.w = rwv*h1.w + cw*v3.y;
        } else {
            float4 p0 = *reinterpret_cast<const float4*>(out + off);
            float4 p1 = *reinterpret_cast<const float4*>(out + off + 4);
            r0.x = p0.x + cw*v0.x; r0.y = p0.y + cw*v0.y;
            r0.z = p0.z + cw*v1.x; r0.w = p0.w + cw*v1.y;
            r1.x = p1.x + cw*v2.x; r1.y = p1.y + cw*v2.y;
            r1.z = p1.z + cw*v3.x; r1.w = p1.w + cw*v3.y;
        }
        *reinterpret_cast<float4*>(out + off)     = r0;
        *reinterpret_cast<float4*>(out + off + 4) = r1;
    }
}

// ---------------- launch ----------------
extern "C" void kernel_launch(void* const* d_in, const int* in_sizes, int n_in,
                              void* d_out, int out_size){
    const float* x   = (const float*)d_in[0];
    const float* W1  = (const float*)d_in[1];
    const float* b1  = (const float*)d_in[2];
    const float* g1  = (const float*)d_in[3];
    const float* be1 = (const float*)d_in[4];
    const float* W2  = (const float*)d_in[5];
    const float* b2  = (const float*)d_in[6];
    const float* g2  = (const float*)d_in[7];
    const float* be2 = (const float*)d_in[8];
    const float* W3  = (const float*)d_in[9];
    const float* b3  = (const float*)d_in[10];
    const float* Wu  = (const float*)d_in[11];
    const float* bu  = (const float*)d_in[12];
    const float* Wv  = (const float*)d_in[13];
    const float* bv  = (const float*)d_in[14];
    const float* su  = (const float*)d_in[15];
    const float* sv  = (const float*)d_in[16];
    const float* rw  = (const float*)d_in[17];
    const float* bt  = (const float*)d_in[18];
    float* out = (float*)d_out;

    k_reset <<<1024, 256>>>();
    k_check <<<(Hn*Hn)/1024, 1024>>>(bt);
    k_rowsq <<<(Bn*Sn)/8, 256>>>(x);
    k_stats <<<512, 256>>>(x);
    k_nrm   <<<64, 256>>>();
    k_feats <<<(Bn*Hn)/256, 256>>>();
    k_fc1   <<<256, 256>>>(W1, b1);
    k_ln1   <<<Bn, 256>>>(g1, be1);
    k_fc2   <<<32, 512>>>(W2, b2);
    k_ln2   <<<Bn, 512>>>(g2, be2);
    k_fc3   <<<16, 256>>>(W3, b3);
    k_uv    <<<1024, 256>>>(Wu, bu, Wv, bv, su, sv);
    k_G     <<<8192, 256>>>(x, bt, rw, out);
    k_F1    <<<512, 256>>>(x);
    k_F2    <<<4096, 256>>>(x, rw, out);
}

// round 6
// speedup vs baseline: 2.2981x; 2.0851x over previous
#include <cuda_runtime.h>
#include <cuda_bf16.h>
#include <cstdint>

#define Bn 4
#define Sn 4096
#define Hn 2048
#define Rn 64
#define HFn (7*Hn)      // 14336
#define HRn (Hn*Rn)     // 131072
#define FINF 3.402823466e+38f

// ---------------- scratch ----------------
__device__ float g_s1[Bn*Hn], g_s2[Bn*Hn], g_s3[Bn*Hn], g_s4[Bn*Hn];
__device__ float g_mx[Bn*Hn], g_mn[Bn*Hn];
__device__ float g_rowsq[Bn*Sn];
__device__ float g_nrm[Bn];
__device__ float g_feats[Bn*HFn];
__device__ float g_h1pre[Bn*1024], g_h1[Bn*1024];
__device__ float g_h2pre[Bn*512], g_h2[Bn*512];
__device__ float g_h3pre[Bn*256];
__device__ float g_U[Bn*HRn];   // U[b]: [H, R] fp32
__device__ float g_V[Bn*HRn];   // V[b]: [R, H] fp32
__device__ __nv_bfloat16 g_Thi[Bn*Sn*Rn];  // T hi, [b][s][r]
__device__ __nv_bfloat16 g_Tlo[Bn*Sn*Rn];  // T lo
__device__ int   g_flag;

// ---------------- helpers ----------------
__device__ __forceinline__ void atomicMaxF(float* a, float v){
    int* ai = (int*)a; int old = *ai;
    while (v > __int_as_float(old)) { old = atomicCAS(ai, old, __float_as_int(v)); }
}
__device__ __forceinline__ void atomicMinF(float* a, float v){
    int* ai = (int*)a; int old = *ai;
    while (v < __int_as_float(old)) { old = atomicCAS(ai, old, __float_as_int(v)); }
}
__device__ __forceinline__ uint32_t s2u(const void* p){
    uint32_t a;
    asm("{ .reg .u64 t; cvta.to.shared.u64 t, %1; cvt.u32.u64 %0, t; }" : "=r"(a) : "l"(p));
    return a;
}
__device__ __forceinline__ void ldsm4(const void* p, uint32_t& r0, uint32_t& r1, uint32_t& r2, uint32_t& r3){
    uint32_t a = s2u(p);
    asm volatile("ldmatrix.sync.aligned.m8n8.x4.shared.b16 {%0,%1,%2,%3}, [%4];"
        : "=r"(r0), "=r"(r1), "=r"(r2), "=r"(r3) : "r"(a));
}
__device__ __forceinline__ void ldsm4t(const void* p, uint32_t& r0, uint32_t& r1, uint32_t& r2, uint32_t& r3){
    uint32_t a = s2u(p);
    asm volatile("ldmatrix.sync.aligned.m8n8.x4.trans.shared.b16 {%0,%1,%2,%3}, [%4];"
        : "=r"(r0), "=r"(r1), "=r"(r2), "=r"(r3) : "r"(a));
}
__device__ __forceinline__ void mma16816(float* d, const uint32_t* a, uint32_t b0, uint32_t b1){
    asm volatile("mma.sync.aligned.m16n8k16.row.col.f32.bf16.bf16.f32 "
        "{%0,%1,%2,%3}, {%4,%5,%6,%7}, {%8,%9}, {%0,%1,%2,%3};"
        : "+f"(d[0]), "+f"(d[1]), "+f"(d[2]), "+f"(d[3])
        : "r"(a[0]), "r"(a[1]), "r"(a[2]), "r"(a[3]), "r"(b0), "r"(b1));
}
__device__ __forceinline__ void split4(float4 v, uint2& hi, uint2& lo){
    __nv_bfloat162 h0 = __floats2bfloat162_rn(v.x, v.y);
    __nv_bfloat162 h1 = __floats2bfloat162_rn(v.z, v.w);
    float2 f0 = __bfloat1622float2(h0);
    float2 f1 = __bfloat1622float2(h1);
    __nv_bfloat162 l0 = __floats2bfloat162_rn(v.x - f0.x, v.y - f0.y);
    __nv_bfloat162 l1 = __floats2bfloat162_rn(v.z - f1.x, v.w - f1.y);
    hi.x = *reinterpret_cast<uint32_t*>(&h0); hi.y = *reinterpret_cast<uint32_t*>(&h1);
    lo.x = *reinterpret_cast<uint32_t*>(&l0); lo.y = *reinterpret_cast<uint32_t*>(&l1);
}
__device__ __forceinline__ uint32_t pack_bf2(float a, float b){
    __nv_bfloat162 h = __floats2bfloat162_rn(a, b);
    return *reinterpret_cast<uint32_t*>(&h);
}

// ---------------- 1. reset ----------------
__global__ void k_reset(){
    int i = blockIdx.x*256 + threadIdx.x;     // grid 32
    if (i == 0) g_flag = 1;
    if (i < Bn*Hn){
        g_s1[i]=0.f; g_s2[i]=0.f; g_s3[i]=0.f; g_s4[i]=0.f;
        g_mx[i]=-FINF; g_mn[i]=FINF;
    }
    if (i < Bn) g_nrm[i]=0.f;
    if (i < Bn*1024) g_h1pre[i]=0.f;
    if (i < Bn*512)  g_h2pre[i]=0.f;
    if (i < Bn*256)  g_h3pre[i]=0.f;
}

// ---------------- 2. identity check ----------------
__global__ __launch_bounds__(1024) void k_check(const float* __restrict__ bt){
    int i = blockIdx.x*1024 + threadIdx.x;
    int r = i / Hn, c = i - r*Hn;
    float expect = (r == c) ? 1.f : 0.f;
    if (bt[i] != expect) g_flag = 0;
}

// ---------------- 3. row sum-of-squares ----------------
__global__ __launch_bounds__(256) void k_rowsq(const float* __restrict__ x){
    int warp = threadIdx.x >> 5, lane = threadIdx.x & 31;
    int row = blockIdx.x*8 + warp;
    const float4* xr = (const float4*)(x + (size_t)row*Hn);
    float acc = 0.f;
    #pragma unroll
    for (int i = 0; i < 16; i++){
        float4 v = __ldg(xr + lane + i*32);
        acc += v.x*v.x + v.y*v.y + v.z*v.z + v.w*v.w;
    }
    #pragma unroll
    for (int o = 16; o > 0; o >>= 1) acc += __shfl_down_sync(0xffffffffu, acc, o);
    if (lane == 0) g_rowsq[row] = acc;
}

// ---------------- 4. column stats ----------------
__global__ __launch_bounds__(256) void k_stats(const float* __restrict__ x){
    const int SCH = 256;
    int blk = blockIdx.x;
    int b  = blk >> 7;
    int ht = (blk >> 4) & 7;
    int sc = blk & 15;
    int h  = ht*256 + threadIdx.x;
    const float* xb = x + ((size_t)b*Sn)*Hn + h;
    float s1=0.f, s2=0.f, s3=0.f, s4=0.f, mx=-FINF, mn=FINF;
    int s0 = sc*SCH;
    #pragma unroll 8
    for (int s = s0; s < s0+SCH; s++){
        float v  = __ldg(xb + (size_t)s*Hn);
        float v2 = v*v;
        s1 += v; s2 += v2; s3 += v2*v; s4 += v2*v2;
        mx = fmaxf(mx, v); mn = fminf(mn, v);
    }
    int idx = b*Hn + h;
    atomicAdd(&g_s1[idx], s1); atomicAdd(&g_s2[idx], s2);
    atomicAdd(&g_s3[idx], s3); atomicAdd(&g_s4[idx], s4);
    atomicMaxF(&g_mx[idx], mx); atomicMinF(&g_mn[idx], mn);
}

// ---------------- 5. norm mean ----------------
__global__ void k_nrm(){
    int b = blockIdx.x >> 4, c = blockIdx.x & 15;
    int s = c*256 + threadIdx.x;
    float v = sqrtf(g_rowsq[b*Sn + s]);
    __shared__ float sm[256];
    sm[threadIdx.x] = v; __syncthreads();
    for (int st = 128; st > 0; st >>= 1){
        if (threadIdx.x < st) sm[threadIdx.x] += sm[threadIdx.x + st];
        __syncthreads();
    }
    if (threadIdx.x == 0) atomicAdd(&g_nrm[b], sm[0]);
}

// ---------------- 6. finalize features ----------------
__global__ void k_feats(){
    int i = blockIdx.x*256 + threadIdx.x;
    int b = i / Hn, h = i - b*Hn;
    const float n = (float)Sn;
    float m1 = g_s1[i]/n, m2 = g_s2[i]/n, m3 = g_s3[i]/n, m4 = g_s4[i]/n;
    float mu2 = m2 - m1*m1; if (mu2 < 0.f) mu2 = 0.f;
    float sd  = sqrtf(mu2 * n/(n-1.f));
    float mu3 = m3 - 3.f*m1*m2 + 2.f*m1*m1*m1;
    float mu4 = m4 - 4.f*m1*m3 + 6.f*m1*m1*m2 - 3.f*m1*m1*m1*m1;
    float skew = mu3 / (sd*sd*sd + 1e-8f);
    float kurt = mu4 / (sd*sd*sd*sd + 1e-8f) - 3.f;
    float* fb = g_feats + (size_t)b*HFn;
    fb[0*Hn+h]=m1; fb[1*Hn+h]=sd; fb[2*Hn+h]=g_nrm[b]*(1.f/n);
    fb[3*Hn+h]=g_mx[i]; fb[4*Hn+h]=g_mn[i]; fb[5*Hn+h]=skew; fb[6*Hn+h]=kurt;
}

// ---------------- 7. fc1 ----------------
__global__ __launch_bounds__(256) void k_fc1(const float* __restrict__ W1, const float* __restrict__ b1){
    const int KC = 224;
    __shared__ float sf[Bn][KC];
    int nt = blockIdx.x >> 6, kc = blockIdx.x & 63;
    int n  = nt*256 + threadIdx.x;
    int k0 = kc*KC;
    for (int l = threadIdx.x; l < Bn*KC; l += 256){
        int bb = l / KC, kk = l - bb*KC;
        sf[bb][kk] = g_feats[(size_t)bb*HFn + k0 + kk];
    }
    __syncthreads();
    float init = (kc == 0) ? __ldg(b1 + n) : 0.f;
    float a0=init, a1=init, a2=init, a3=init;
    #pragma unroll 8
    for (int kk = 0; kk < KC; kk++){
        float w = __ldg(W1 + (size_t)(k0+kk)*1024 + n);
        a0 += sf[0][kk]*w; a1 += sf[1][kk]*w; a2 += sf[2][kk]*w; a3 += sf[3][kk]*w;
    }
    atomicAdd(&g_h1pre[0*1024+n], a0); atomicAdd(&g_h1pre[1*1024+n], a1);
    atomicAdd(&g_h1pre[2*1024+n], a2); atomicAdd(&g_h1pre[3*1024+n], a3);
}

// ---------------- 8. LN1 + ReLU ----------------
__global__ void k_ln1(const float* __restrict__ g1, const float* __restrict__ be1){
    int b = blockIdx.x;
    float v[4], s = 0.f, ss = 0.f;
    #pragma unroll
    for (int i = 0; i < 4; i++){
        v[i] = g_h1pre[b*1024 + i*256 + threadIdx.x];
        s += v[i]; ss += v[i]*v[i];
    }
    __shared__ float r1[256], r2[256];
    r1[threadIdx.x]=s; r2[threadIdx.x]=ss; __syncthreads();
    for (int st = 128; st > 0; st >>= 1){
        if (threadIdx.x < st){ r1[threadIdx.x]+=r1[threadIdx.x+st]; r2[threadIdx.x]+=r2[threadIdx.x+st]; }
        __syncthreads();
    }
    float mean = r1[0]/1024.f, var = r2[0]/1024.f - mean*mean;
    float inv = rsqrtf(var + 1e-5f);
    #pragma unroll
    for (int i = 0; i < 4; i++){
        int idx = i*256 + threadIdx.x;
        float y = (v[i]-mean)*inv*__ldg(g1+idx) + __ldg(be1+idx);
        g_h1[b*1024+idx] = fmaxf(y, 0.f);
    }
}

// ---------------- 9. fc2 ----------------
__global__ __launch_bounds__(512) void k_fc2(const float* __restrict__ W2, const float* __restrict__ b2){
    int b = blockIdx.x >> 3, kc = blockIdx.x & 7;
    int n = threadIdx.x;
    __shared__ float sh[128];
    if (n < 128) sh[n] = g_h1[b*1024 + kc*128 + n];
    __syncthreads();
    float acc = (kc == 0) ? __ldg(b2 + n) : 0.f;
    #pragma unroll 8
    for (int k = 0; k < 128; k++)
        acc += sh[k]*__ldg(W2 + (size_t)(kc*128+k)*512 + n);
    atomicAdd(&g_h2pre[b*512+n], acc);
}

// ---------------- 10. LN2 + ReLU ----------------
__global__ __launch_bounds__(512) void k_ln2(const float* __restrict__ g2, const float* __restrict__ be2){
    int b = blockIdx.x, n = threadIdx.x;
    float acc = g_h2pre[b*512+n];
    __shared__ float r1[512], r2[512];
    r1[n]=acc; r2[n]=acc*acc; __syncthreads();
    for (int st = 256; st > 0; st >>= 1){
        if (n < st){ r1[n]+=r1[n+st]; r2[n]+=r2[n+st]; }
        __syncthreads();
    }
    float mean = r1[0]/512.f, var = r2[0]/512.f - mean*mean;
    float y = (acc-mean)*rsqrtf(var+1e-5f)*__ldg(g2+n) + __ldg(be2+n);
    g_h2[b*512+n] = fmaxf(y, 0.f);
}

// ---------------- 11. fc3 ----------------
__global__ __launch_bounds__(256) void k_fc3(const float* __restrict__ W3, const float* __restrict__ b3){
    int b = blockIdx.x >> 2, kc = blockIdx.x & 3;
    int n = threadIdx.x;
    __shared__ float sh[128];
    if (n < 128) sh[n] = g_h2[b*512 + kc*128 + n];
    __syncthreads();
    float acc = (kc == 0) ? __ldg(b3 + n) : 0.f;
    #pragma unroll 8
    for (int k = 0; k < 128; k++)
        acc += sh[k]*__ldg(W3 + (size_t)(kc*128+k)*256 + n);
    atomicAdd(&g_h3pre[b*256+n], acc);
}

// ---------------- 12. U,V generation ----------------
__global__ __launch_bounds__(256) void k_uv(const float* __restrict__ Wu, const float* __restrict__ bu,
                                            const float* __restrict__ Wv, const float* __restrict__ bv,
                                            const float* __restrict__ su, const float* __restrict__ sv){
    __shared__ float sh[Bn*256];
    for (int i = threadIdx.x; i < Bn*256; i += 256) sh[i] = fmaxf(g_h3pre[i], 0.f);
    __syncthreads();
    int half = blockIdx.x >> 9;
    int j = ((blockIdx.x & 511)*256) + threadIdx.x;
    const float* W  = half ? Wv : Wu;
    const float* bb = half ? bv : bu;
    float sc = half ? __ldg(sv) : __ldg(su);
    float a0 = __ldg(bb + j); float a1=a0, a2=a0, a3=a0;
    #pragma unroll 8
    for (int k = 0; k < 256; k++){
        float w = __ldg(W + (size_t)k*HRn + j);
        a0 += sh[0*256+k]*w; a1 += sh[1*256+k]*w; a2 += sh[2*256+k]*w; a3 += sh[3*256+k]*w;
    }
    float* O = half ? g_V : g_U;
    O[0*(size_t)HRn+j]=a0*sc; O[1*(size_t)HRn+j]=a1*sc;
    O[2*(size_t)HRn+j]=a2*sc; O[3*(size_t)HRn+j]=a3*sc;
}

// ---------------- 13. general-base fallback (no-op when identity) ----------------
__global__ __launch_bounds__(256) void k_G(const float* __restrict__ x, const float* __restrict__ bt,
                                           const float* __restrict__ rw_p, float* __restrict__ out){
    if (g_flag) return;
    __shared__ float As[64][65];
    __shared__ float Bs[64][65];
    int blk = blockIdx.x;
    int b  = blk / 2048;
    int rem = blk - b*2048;
    int st = rem >> 5;
    int nt = rem & 31;
    int tid = threadIdx.x, tx = tid & 15, ty = tid >> 4;
    const float* xb = x + ((size_t)b*Sn + st*64)*Hn;
    float acc[4][4] = {};
    for (int kt = 0; kt < 32; kt++){
        #pragma unroll
        for (int r = 0; r < 16; r++){
            int l = r*256 + tid; int i = l >> 6, j = l & 63;
            As[i][j] = xb[(size_t)i*Hn + kt*64 + j];
            Bs[i][j] = bt[(size_t)(kt*64+i)*Hn + nt*64 + j];
        }
        __syncthreads();
        #pragma unroll
        for (int kk = 0; kk < 64; kk++){
            float a[4], bv[4];
            #pragma unroll
            for (int i = 0; i < 4; i++) a[i]  = As[ty*4+i][kk];
            #pragma unroll
            for (int j = 0; j < 4; j++) bv[j] = Bs[kk][tx*4+j];
            #pragma unroll
            for (int i = 0; i < 4; i++)
                #pragma unroll
                for (int j = 0; j < 4; j++) acc[i][j] += a[i]*bv[j];
        }
        __syncthreads();
    }
    float rwv = __ldg(rw_p);
    size_t base = ((size_t)b*Sn + st*64)*Hn + nt*64;
    #pragma unroll
    for (int i = 0; i < 4; i++)
        #pragma unroll
        for (int j = 0; j < 4; j++)
            out[base + (size_t)(ty*4+i)*Hn + tx*4+j] = rwv*acc[i][j];
}

// ================= 14. F1: T = x @ U  (mma.sync bf16, hi/lo 3-term) =================
// grid = Bn*32 = 128 CTAs, 256 threads (8 warps, 4m x 2n). M=128, N=64, K=2048 (32 chunks of 64).
#define PA1 72
#define PB1 72
#define F1_SMEM ((128*PA1*2 + 64*PB1*2)*2)   // bytes: Ah,Al,Bh,Bl

__global__ __launch_bounds__(256) void k_F1(const float* __restrict__ x){
    extern __shared__ __nv_bfloat16 sm1[];
    __nv_bfloat16* Ah = sm1;
    __nv_bfloat16* Al = Ah + 128*PA1;
    __nv_bfloat16* Bh = Al + 128*PA1;
    __nv_bfloat16* Bl = Bh + 64*PB1;
    int tid = threadIdx.x, lane = tid & 31, wid = tid >> 5;
    int wm = wid >> 1, wn = wid & 1;
    int b = blockIdx.x >> 5, st = blockIdx.x & 31;
    const float* xb = x + ((size_t)b*Sn + st*128)*Hn;
    const float* Ub = g_U + (size_t)b*HRn;

    int arow = tid >> 4, ac4 = tid & 15;     // A load mapping
    float acc[2][4][4] = {};
    float4 av[8], bvv[4];
    // prefetch chunk 0
    #pragma unroll
    for (int p = 0; p < 8; p++)
        av[p] = __ldg((const float4*)(xb + (size_t)(p*16 + arow)*Hn) + ac4);
    #pragma unroll
    for (int it = 0; it < 4; it++)
        bvv[it] = __ldg((const float4*)(Ub + (size_t)(it*16 + arow)*Rn) + ac4);

    for (int kt = 0; kt < 32; kt++){
        // store current chunk to smem (hi/lo split)
        #pragma unroll
        for (int p = 0; p < 8; p++){
            int row = p*16 + arow;
            uint2 hi, lo; split4(av[p], hi, lo);
            *(uint2*)(Ah + row*PA1 + ac4*4) = hi;
            *(uint2*)(Al + row*PA1 + ac4*4) = lo;
        }
        #pragma unroll
        for (int it = 0; it < 4; it++){
            int row = it*16 + arow;
            uint2 hi, lo; split4(bvv[it], hi, lo);
            *(uint2*)(Bh + row*PB1 + ac4*4) = hi;
            *(uint2*)(Bl + row*PB1 + ac4*4) = lo;
        }
        __syncthreads();
        // prefetch next chunk (overlaps mma)
        if (kt < 31){
            #pragma unroll
            for (int p = 0; p < 8; p++)
                av[p] = __ldg((const float4*)(xb + (size_t)(p*16 + arow)*Hn + (kt+1)*64) + ac4);
            #pragma unroll
            for (int it = 0; it < 4; it++)
                bvv[it] = __ldg((const float4*)(Ub + (size_t)((kt+1)*64 + it*16 + arow)*Rn) + ac4);
        }
        #pragma unroll
        for (int ks = 0; ks < 4; ks++){
            uint32_t ah[2][4], al[2][4];
            #pragma unroll
            for (int mi = 0; mi < 2; mi++){
                int r = wm*32 + mi*16 + (lane & 15);
                int c = ks*16 + (lane >> 4)*8;
                ldsm4(Ah + r*PA1 + c, ah[mi][0], ah[mi][1], ah[mi][2], ah[mi][3]);
                ldsm4(Al + r*PA1 + c, al[mi][0], al[mi][1], al[mi][2], al[mi][3]);
            }
            #pragma unroll
            for (int ng = 0; ng < 2; ng++){
                int n0 = wn*32 + ng*16;
                int r = ks*16 + (lane & 15);
                int c = n0 + (lane >> 4)*8;
                uint32_t bh0, bh1, bh2, bh3, bl0, bl1, bl2, bl3;
                ldsm4t(Bh + r*PB1 + c, bh0, bh1, bh2, bh3);
                ldsm4t(Bl + r*PB1 + c, bl0, bl1, bl2, bl3);
                #pragma unroll
                for (int mi = 0; mi < 2; mi++){
                    mma16816(acc[mi][ng*2+0], ah[mi], bh0, bh1);
                    mma16816(acc[mi][ng*2+0], ah[mi], bl0, bl1);
                    mma16816(acc[mi][ng*2+0], al[mi], bh0, bh1);
                    mma16816(acc[mi][ng*2+1], ah[mi], bh2, bh3);
                    mma16816(acc[mi][ng*2+1], ah[mi], bl2, bl3);
                    mma16816(acc[mi][ng*2+1], al[mi], bh2, bh3);
                }
            }
        }
        __syncthreads();
    }
    // epilogue: write T as bf16 hi/lo
    int g = lane >> 2, tg = lane & 3;
    __nv_bfloat16* Tb_h = g_Thi + ((size_t)b*Sn + st*128)*Rn;
    __nv_bfloat16* Tb_l = g_Tlo + ((size_t)b*Sn + st*128)*Rn;
    #pragma unroll
    for (int mi = 0; mi < 2; mi++){
        int r0 = wm*32 + mi*16 + g;
        #pragma unroll
        for (int ni = 0; ni < 4; ni++){
            int c = wn*32 + ni*8 + tg*2;
            float* a = acc[mi][ni];
            // row r0: a[0], a[1]
            float h0 = __bfloat162float(__float2bfloat16(a[0]));
            float h1 = __bfloat162float(__float2bfloat16(a[1]));
            *(uint32_t*)(Tb_h + (size_t)r0*Rn + c) = pack_bf2(a[0], a[1]);
            *(uint32_t*)(Tb_l + (size_t)r0*Rn + c) = pack_bf2(a[0]-h0, a[1]-h1);
            // row r0+8: a[2], a[3]
            float h2 = __bfloat162float(__float2bfloat16(a[2]));
            float h3 = __bfloat162float(__float2bfloat16(a[3]));
            *(uint32_t*)(Tb_h + (size_t)(r0+8)*Rn + c) = pack_bf2(a[2], a[3]);
            *(uint32_t*)(Tb_l + (size_t)(r0+8)*Rn + c) = pack_bf2(a[2]-h2, a[3]-h3);
        }
    }
}

// ================= 15. F2: out = rw*x + cw*(T @ V)  (mma.sync bf16) =================
// grid = Bn*32*16 = 2048 CTAs, 256 threads. M=128, N=128, K=64.
#define PA2 72
#define PB2 136
#define F2_SMEM ((128*PA2*2 + 64*PB2*2)*2)

__global__ __launch_bounds__(256) void k_F2(const float* __restrict__ x, const float* __restrict__ rw_p,
                                            float* __restrict__ out){
    extern __shared__ __nv_bfloat16 sm2[];
    __nv_bfloat16* Ah = sm2;
    __nv_bfloat16* Al = Ah + 128*PA2;
    __nv_bfloat16* Bh = Al + 128*PA2;
    __nv_bfloat16* Bl = Bh + 64*PB2;
    int tid = threadIdx.x, lane = tid & 31, wid = tid >> 5;
    int wm = wid >> 1, wn = wid & 1;
    int b = blockIdx.x >> 9;
    int rem = blockIdx.x & 511;
    int st = rem >> 4, nt = rem & 15;

    // A: T tile [128 x 64] bf16 hi/lo (already split) — straight copy
    const __nv_bfloat16* Th = g_Thi + ((size_t)b*Sn + st*128)*Rn;
    const __nv_bfloat16* Tl = g_Tlo + ((size_t)b*Sn + st*128)*Rn;
    #pragma unroll
    for (int it = 0; it < 4; it++){
        int idx = it*256 + tid; int row = idx >> 3, ch = idx & 7;
        uint4 h = __ldg((const uint4*)(Th + (size_t)row*Rn) + ch);
        uint4 l = __ldg((const uint4*)(Tl + (size_t)row*Rn) + ch);
        *(uint4*)(Ah + row*PA2 + ch*8) = h;
        *(uint4*)(Al + row*PA2 + ch*8) = l;
    }
    // B: V tile [64 k-rows x 128 n-cols] fp32 -> hi/lo bf16
    const float* Vb = g_V + (size_t)b*HRn + nt*128;
    #pragma unroll
    for (int it = 0; it < 8; it++){
        int idx = it*256 + tid; int row = idx >> 5, c4 = idx & 31;
        float4 v = __ldg((const float4*)(Vb + (size_t)row*Hn) + c4);
        uint2 hi, lo; split4(v, hi, lo);
        *(uint2*)(Bh + row*PB2 + c4*4) = hi;
        *(uint2*)(Bl + row*PB2 + c4*4) = lo;
    }
    __syncthreads();

    float acc[2][8][4] = {};
    #pragma unroll
    for (int ks = 0; ks < 4; ks++){
        uint32_t ah[2][4], al[2][4];
        #pragma unroll
        for (int mi = 0; mi < 2; mi++){
            int r = wm*32 + mi*16 + (lane & 15);
            int c = ks*16 + (lane >> 4)*8;
            ldsm4(Ah + r*PA2 + c, ah[mi][0], ah[mi][1], ah[mi][2], ah[mi][3]);
            ldsm4(Al + r*PA2 + c, al[mi][0], al[mi][1], al[mi][2], al[mi][3]);
        }
        #pragma unroll
        for (int ng = 0; ng < 4; ng++){
            int n0 = wn*64 + ng*16;
            int r = ks*16 + (lane & 15);
            int c = n0 + (lane >> 4)*8;
            uint32_t bh0, bh1, bh2, bh3, bl0, bl1, bl2, bl3;
            ldsm4t(Bh + r*PB2 + c, bh0, bh1, bh2, bh3);
            ldsm4t(Bl + r*PB2 + c, bl0, bl1, bl2, bl3);
            #pragma unroll
            for (int mi = 0; mi < 2; mi++){
                mma16816(acc[mi][ng*2+0], ah[mi], bh0, bh1);
                mma16816(acc[mi][ng*2+0], ah[mi], bl0, bl1);
                mma16816(acc[mi][ng*2+0], al[mi], bh0, bh1);
                mma16816(acc[mi][ng*2+1], ah[mi], bh2, bh3);
                mma16816(acc[mi][ng*2+1], ah[mi], bl2, bl3);
                mma16816(acc[mi][ng*2+1], al[mi], bh2, bh3);
            }
        }
    }

    float rwv = __ldg(rw_p);
    float cw  = 1.f - rwv;
    bool ident = (g_flag != 0);
    int g = lane >> 2, tg = lane & 3;
    #pragma unroll
    for (int mi = 0; mi < 2; mi++){
        int r0 = st*128 + wm*32 + mi*16 + g;
        #pragma unroll
        for (int ni = 0; ni < 8; ni++){
            int c = nt*128 + wn*64 + ni*8 + tg*2;
            float* a = acc[mi][ni];
            size_t o0 = ((size_t)b*Sn + r0)*Hn + c;
            size_t o1 = o0 + (size_t)8*Hn;
            float2 r00, r11;
            if (ident){
                float2 h0 = *(const float2*)(x + o0);
                float2 h1 = *(const float2*)(x + o1);
                r00.x = rwv*h0.x + cw*a[0]; r00.y = rwv*h0.y + cw*a[1];
                r11.x = rwv*h1.x + cw*a[2]; r11.y = rwv*h1.y + cw*a[3];
            } else {
                float2 p0 = *(const float2*)(out + o0);
                float2 p1 = *(const float2*)(out + o1);
                r00.x = p0.x + cw*a[0]; r00.y = p0.y + cw*a[1];
                r11.x = p1.x + cw*a[2]; r11.y = p1.y + cw*a[3];
            }
            *(float2*)(out + o0) = r00;
            *(float2*)(out + o1) = r11;
        }
    }
}

// ---------------- launch ----------------
extern "C" void kernel_launch(void* const* d_in, const int* in_sizes, int n_in,
                              void* d_out, int out_size){
    const float* x   = (const float*)d_in[0];
    const float* W1  = (const float*)d_in[1];
    const float* b1  = (const float*)d_in[2];
    const float* g1  = (const float*)d_in[3];
    const float* be1 = (const float*)d_in[4];
    const float* W2  = (const float*)d_in[5];
    const float* b2  = (const float*)d_in[6];
    const float* g2  = (const float*)d_in[7];
    const float* be2 = (const float*)d_in[8];
    const float* W3  = (const float*)d_in[9];
    const float* b3  = (const float*)d_in[10];
    const float* Wu  = (const float*)d_in[11];
    const float* bu  = (const float*)d_in[12];
    const float* Wv  = (const float*)d_in[13];
    const float* bv  = (const float*)d_in[14];
    const float* su  = (const float*)d_in[15];
    const float* sv  = (const float*)d_in[16];
    const float* rw  = (const float*)d_in[17];
    const float* bt  = (const float*)d_in[18];
    float* out = (float*)d_out;

    cudaFuncSetAttribute(k_F1, cudaFuncAttributeMaxDynamicSharedMemorySize, F1_SMEM);
    cudaFuncSetAttribute(k_F2, cudaFuncAttributeMaxDynamicSharedMemorySize, F2_SMEM);

    k_reset <<<32, 256>>>();
    k_check <<<(Hn*Hn)/1024, 1024>>>(bt);
    k_rowsq <<<(Bn*Sn)/8, 256>>>(x);
    k_stats <<<512, 256>>>(x);
    k_nrm   <<<64, 256>>>();
    k_feats <<<(Bn*Hn)/256, 256>>>();
    k_fc1   <<<256, 256>>>(W1, b1);
    k_ln1   <<<Bn, 256>>>(g1, be1);
    k_fc2   <<<32, 512>>>(W2, b2);
    k_ln2   <<<Bn, 512>>>(g2, be2);
    k_fc3   <<<16, 256>>>(W3, b3);
    k_uv    <<<1024, 256>>>(Wu, bu, Wv, bv, su, sv);
    k_G     <<<8192, 256>>>(x, bt, rw, out);
    k_F1    <<<Bn*32, 256, F1_SMEM>>>(x);
    k_F2    <<<Bn*32*16, 256, F2_SMEM>>>(x, rw, out);
}